// round 16
// baseline (speedup 1.0000x reference)
#include <cuda_runtime.h>

// out[b,o] = sum_{i<64, l<32} obs[b,i,l,o] * ctx[b, 31-l, i]
// obs[b] flattened over (i,l,o) is contiguous: float4 index = p*16 + o4,
// p = i*32 + l, o4 = o/4.
// One CTA per b, 256 threads = 8 warps. Per iteration each warp consumes
// 64 consecutive float4s (1024B): thread loads idx and idx+32 (two LDG.128).
// j=0 obs loads are hoisted ABOVE ctx staging + barrier (manual prefetch):
// the obs stream starts at CTA cycle ~0 instead of after the prologue.
// Lanes l and l+16 hold the SAME o-range -> shfl folds warp to 8 partials.

#define B_DIM 2048
#define R_DIM 32
#define O_DIM 64
#define PAIRS 2048            // 64*32
#define JITERS 64             // 2048 p's / (8 warps * 4 p's per warp-iter)

__global__ __launch_bounds__(256, 8)
void cnnkf_kernel(const float* __restrict__ ctx,
                  const float* __restrict__ obs,
                  float* __restrict__ out) {
    __shared__ float s_ctx[R_DIM * O_DIM];       // 8 KB: ctx[b] row-major [r][i]
    __shared__ float s_part[8][O_DIM];           // 2 KB: 8 partials per o

    const int b   = blockIdx.x;
    const int tid = threadIdx.x;

    const float* __restrict__ ctx_b = ctx + (size_t)b * (R_DIM * O_DIM);
    const float* __restrict__ obs_b = obs + (size_t)b * (size_t)(PAIRS * O_DIM);

    const int warp = tid >> 5;    // 0..7
    const int lane = tid & 31;    // 0..31
    const int o4   = lane & 15;   // o = o4*4 .. o4*4+3

    const float4* __restrict__ base = reinterpret_cast<const float4*>(obs_b);

    // ---- Prefetch j=0 obs loads BEFORE the prologue barrier ----
    const int pidx = warp * 64 + lane;            // j=0 index
    const float4 pv0 = __ldcs(&base[pidx]);
    const float4 pv1 = __ldcs(&base[pidx + 32]);

    // Stage context slice (2048 floats) as float4: 2 passes of 256 LDG.128.
    {
        const float4* __restrict__ csrc = reinterpret_cast<const float4*>(ctx_b);
        float4* __restrict__ cdst = reinterpret_cast<float4*>(s_ctx);
        cdst[tid]       = csrc[tid];
        cdst[tid + 256] = csrc[tid + 256];
    }
    __syncthreads();

    float4 acc = make_float4(0.f, 0.f, 0.f, 0.f);

    // ---- Consume prefetched j=0 ----
    {
        const int p0 = pidx >> 4;
        const int p1 = p0 + 2;
        const float c0 = s_ctx[(31 - (p0 & 31)) * O_DIM + (p0 >> 5)];
        const float c1 = s_ctx[(31 - (p1 & 31)) * O_DIM + (p1 >> 5)];
        acc.x = fmaf(c0, pv0.x, acc.x);
        acc.y = fmaf(c0, pv0.y, acc.y);
        acc.z = fmaf(c0, pv0.z, acc.z);
        acc.w = fmaf(c0, pv0.w, acc.w);
        acc.x = fmaf(c1, pv1.x, acc.x);
        acc.y = fmaf(c1, pv1.y, acc.y);
        acc.z = fmaf(c1, pv1.z, acc.z);
        acc.w = fmaf(c1, pv1.w, acc.w);
    }

    #pragma unroll 7
    for (int j = 1; j < JITERS; j++) {
        // Warp covers float4 indices [j*512 + warp*64, +64): 1024B contiguous.
        const int idx0 = j * 512 + warp * 64 + lane;
        const float4 v0 = __ldcs(&base[idx0]);        // p0 = idx0 >> 4
        const float4 v1 = __ldcs(&base[idx0 + 32]);   // p1 = p0 + 2
        const int p0 = idx0 >> 4;
        const int l0 = p0 & 31;
        const int i0 = p0 >> 5;
        const int p1 = p0 + 2;
        const int l1 = p1 & 31;
        const int i1 = p1 >> 5;
        const float c0 = s_ctx[(31 - l0) * O_DIM + i0];
        const float c1 = s_ctx[(31 - l1) * O_DIM + i1];
        acc.x = fmaf(c0, v0.x, acc.x);
        acc.y = fmaf(c0, v0.y, acc.y);
        acc.z = fmaf(c0, v0.z, acc.z);
        acc.w = fmaf(c0, v0.w, acc.w);
        acc.x = fmaf(c1, v1.x, acc.x);
        acc.y = fmaf(c1, v1.y, acc.y);
        acc.z = fmaf(c1, v1.z, acc.z);
        acc.w = fmaf(c1, v1.w, acc.w);
    }

    // Intra-warp fold: lane and lane+16 hold the same o-range.
    acc.x += __shfl_down_sync(0xFFFFFFFFu, acc.x, 16);
    acc.y += __shfl_down_sync(0xFFFFFFFFu, acc.y, 16);
    acc.z += __shfl_down_sync(0xFFFFFFFFu, acc.z, 16);
    acc.w += __shfl_down_sync(0xFFFFFFFFu, acc.w, 16);

    if (lane < 16) {
        *reinterpret_cast<float4*>(&s_part[warp][o4 * 4]) = acc;
    }
    __syncthreads();

    // Cross-warp reduction: 64 threads, then 16 float4 STGs.
    if (tid < O_DIM) {
        float s = s_part[0][tid];
        #pragma unroll
        for (int g = 1; g < 8; g++) s += s_part[g][tid];
        s_part[0][tid] = s;          // reuse row 0 as the result row
    }
    __syncthreads();
    if (tid < 16) {
        reinterpret_cast<float4*>(out + (size_t)b * O_DIM)[tid] =
            reinterpret_cast<const float4*>(&s_part[0][0])[tid];
    }
}

extern "C" void kernel_launch(void* const* d_in, const int* in_sizes, int n_in,
                              void* d_out, int out_size) {
    const float* ctx = (const float*)d_in[0];   // context      (B, R, O)
    const float* obs = (const float*)d_in[1];   // observation  (B, O, R, O)
    float* out = (float*)d_out;                  // (B, O)

    cnnkf_kernel<<<B_DIM, 256>>>(ctx, obs, out);
}

// round 17
// speedup vs baseline: 1.0284x; 1.0284x over previous
#include <cuda_runtime.h>

// out[b,o] = sum_{i<64, l<32} obs[b,i,l,o] * ctx[b, 31-l, i]
// obs[b] flattened over (i,l,o) is contiguous: float4 index = p*16 + o4,
// p = i*32 + l, o4 = o/4.
// One CTA per b, 256 threads = 8 warps. Per iteration each warp consumes
// 64 consecutive float4s (1024B): thread loads idx and idx+32 (two LDG.128).
// Lanes l and l+16 hold the SAME o-range -> one shfl folds the warp to 8
// partial streams, halving the smem epilogue. Output stored as float4.
// (R14 configuration — best measured: 152.1us, DRAM 89.4%, 7.08 TB/s.)

#define B_DIM 2048
#define R_DIM 32
#define O_DIM 64
#define PAIRS 2048            // 64*32
#define JITERS 64             // 2048 p's / (8 warps * 4 p's per warp-iter)

__global__ __launch_bounds__(256, 8)
void cnnkf_kernel(const float* __restrict__ ctx,
                  const float* __restrict__ obs,
                  float* __restrict__ out) {
    __shared__ float s_ctx[R_DIM * O_DIM];       // 8 KB: ctx[b] row-major [r][i]
    __shared__ float s_part[8][O_DIM];           // 2 KB: 8 partials per o

    const int b   = blockIdx.x;
    const int tid = threadIdx.x;

    const float* __restrict__ ctx_b = ctx + (size_t)b * (R_DIM * O_DIM);
    const float* __restrict__ obs_b = obs + (size_t)b * (size_t)(PAIRS * O_DIM);

    // Stage context slice (2048 floats) into smem, coalesced.
    #pragma unroll
    for (int k = 0; k < (R_DIM * O_DIM) / 256; k++) {
        s_ctx[k * 256 + tid] = ctx_b[k * 256 + tid];
    }
    __syncthreads();

    const int warp = tid >> 5;    // 0..7
    const int lane = tid & 31;    // 0..31
    const int o4   = lane & 15;   // o = o4*4 .. o4*4+3

    float4 acc = make_float4(0.f, 0.f, 0.f, 0.f);

    const float4* __restrict__ base = reinterpret_cast<const float4*>(obs_b);

    #pragma unroll 8
    for (int j = 0; j < JITERS; j++) {
        // Warp covers float4 indices [j*512 + warp*64, +64): 1024B contiguous.
        const int idx0 = j * 512 + warp * 64 + lane;
        const float4 v0 = __ldcs(&base[idx0]);        // p0 = idx0 >> 4
        const float4 v1 = __ldcs(&base[idx0 + 32]);   // p1 = p0 + 2
        const int p0 = idx0 >> 4;
        const int l0 = p0 & 31;
        const int i0 = p0 >> 5;
        const int p1 = p0 + 2;
        const int l1 = p1 & 31;
        const int i1 = p1 >> 5;
        const float c0 = s_ctx[(31 - l0) * O_DIM + i0];
        const float c1 = s_ctx[(31 - l1) * O_DIM + i1];
        acc.x = fmaf(c0, v0.x, acc.x);
        acc.y = fmaf(c0, v0.y, acc.y);
        acc.z = fmaf(c0, v0.z, acc.z);
        acc.w = fmaf(c0, v0.w, acc.w);
        acc.x = fmaf(c1, v1.x, acc.x);
        acc.y = fmaf(c1, v1.y, acc.y);
        acc.z = fmaf(c1, v1.z, acc.z);
        acc.w = fmaf(c1, v1.w, acc.w);
    }

    // Intra-warp fold: lane and lane+16 hold the same o-range.
    acc.x += __shfl_down_sync(0xFFFFFFFFu, acc.x, 16);
    acc.y += __shfl_down_sync(0xFFFFFFFFu, acc.y, 16);
    acc.z += __shfl_down_sync(0xFFFFFFFFu, acc.z, 16);
    acc.w += __shfl_down_sync(0xFFFFFFFFu, acc.w, 16);

    if (lane < 16) {
        *reinterpret_cast<float4*>(&s_part[warp][o4 * 4]) = acc;
    }
    __syncthreads();

    // Cross-warp reduction: 64 threads, then 16 float4 STGs.
    if (tid < O_DIM) {
        float s = s_part[0][tid];
        #pragma unroll
        for (int g = 1; g < 8; g++) s += s_part[g][tid];
        s_part[0][tid] = s;          // reuse row 0 as the result row
    }
    __syncthreads();
    if (tid < 16) {
        reinterpret_cast<float4*>(out + (size_t)b * O_DIM)[tid] =
            reinterpret_cast<const float4*>(&s_part[0][0])[tid];
    }
}

extern "C" void kernel_launch(void* const* d_in, const int* in_sizes, int n_in,
                              void* d_out, int out_size) {
    const float* ctx = (const float*)d_in[0];   // context      (B, R, O)
    const float* obs = (const float*)d_in[1];   // observation  (B, O, R, O)
    float* out = (float*)d_out;                  // (B, O)

    cnnkf_kernel<<<B_DIM, 256>>>(ctx, obs, out);
}